// round 1
// baseline (speedup 1.0000x reference)
#include <cuda_runtime.h>
#include <math.h>

#define B_    128
#define NP_   256
#define NN    (B_*NP_)       // 32768
#define H_    128
#define DIMS_ 128
#define HEADS_ 8
#define DK_   16
#define C1_   32
#define C2_   64
#define NC_   10

// ------------------- device scratch (no allocations allowed) -------------------
__device__ float g_deg[NN];
__device__ float g_dnorm[NN];
__device__ float g_A[(size_t)B_*NP_*NP_];            // 33.5 MB dense normalized adjacency
__device__ float g_pre[(size_t)NN*H_];               // h @ W
__device__ float g_h[(size_t)NN*H_];                 // current node features
__device__ float g_sp[NN];                           // h @ W_p
__device__ float g_score[NN];                        // A_hat @ sp + b_p
__device__ float g_feats[(size_t)3*B_*DIMS_*H_];     // pooled feats / attention out per layer
__device__ float g_q[(size_t)B_*DIMS_*H_];
__device__ float g_k[(size_t)B_*DIMS_*H_];
__device__ float g_v[(size_t)B_*DIMS_*H_];

// ------------------- small prep kernels -------------------
__global__ void zero_kernel() {
    size_t i = (size_t)blockIdx.x * blockDim.x + threadIdx.x;
    size_t nA = (size_t)B_*NP_*NP_;
    if (i < nA) g_A[i] = 0.f;
    if (i < NN) g_deg[i] = 0.f;
}

__global__ void deg_kernel(const int* __restrict__ dst, int E) {
    int e = blockIdx.x * blockDim.x + threadIdx.x;
    if (e < E) atomicAdd(&g_deg[dst[e]], 1.0f);
}

__global__ void dnorm_kernel() {
    int i = blockIdx.x * blockDim.x + threadIdx.x;
    if (i < NN) g_dnorm[i] = rsqrtf(fmaxf(g_deg[i], 1.0f));
}

__global__ void buildA_kernel(const int* __restrict__ src, const int* __restrict__ dst, int E) {
    int e = blockIdx.x * blockDim.x + threadIdx.x;
    if (e < E) {
        int s = src[e], d = dst[e];
        int g  = d >> 8;              // NP_ = 256
        int sl = s & 255, dl = d & 255;
        atomicAdd(&g_A[((size_t)g*NP_ + dl)*NP_ + sl], g_dnorm[s]*g_dnorm[d]);
    }
}

// ------------------- generic fp32 tiled GEMM: C = act(A @ W + bias) -------------------
// block: 256 threads, 64x64 tile, each thread 4x4. K, M, N multiples of 16/64.
__global__ void gemm_kernel(const float* __restrict__ A, const float* __restrict__ W,
                            const float* __restrict__ bias, float* __restrict__ C,
                            int M, int Nn, int K,
                            long long sA, long long sB, long long sC, int relu)
{
    const float* Ab = A + (size_t)blockIdx.z * sA;
    const float* Wb = W + (size_t)blockIdx.z * sB;
    float*       Cb = C + (size_t)blockIdx.z * sC;
    int m0 = blockIdx.x * 64;
    int n0 = blockIdx.y * 64;
    __shared__ float As[16][65];
    __shared__ float Bs[16][64];
    int tid = threadIdx.x;
    int tx = tid & 15, ty = tid >> 4;
    float acc[4][4];
    #pragma unroll
    for (int i = 0; i < 4; i++)
        #pragma unroll
        for (int j = 0; j < 4; j++) acc[i][j] = 0.f;

    for (int k0 = 0; k0 < K; k0 += 16) {
        #pragma unroll
        for (int r = 0; r < 4; r++) {
            int e = tid + 256*r;
            int kk = e & 15, m = e >> 4;
            As[kk][m] = Ab[(size_t)(m0+m)*K + k0 + kk];
        }
        #pragma unroll
        for (int r = 0; r < 4; r++) {
            int e = tid + 256*r;
            int n = e & 63, kk = e >> 6;
            Bs[kk][n] = Wb[(size_t)(k0+kk)*Nn + n0 + n];
        }
        __syncthreads();
        #pragma unroll
        for (int kk = 0; kk < 16; kk++) {
            float a[4], b[4];
            #pragma unroll
            for (int i = 0; i < 4; i++) a[i] = As[kk][ty*4+i];
            #pragma unroll
            for (int j = 0; j < 4; j++) b[j] = Bs[kk][tx*4+j];
            #pragma unroll
            for (int i = 0; i < 4; i++)
                #pragma unroll
                for (int j = 0; j < 4; j++) acc[i][j] += a[i]*b[j];
        }
        __syncthreads();
    }
    float bv[4] = {0.f,0.f,0.f,0.f};
    if (bias) {
        #pragma unroll
        for (int j = 0; j < 4; j++) bv[j] = bias[n0 + tx*4 + j];
    }
    #pragma unroll
    for (int i = 0; i < 4; i++) {
        #pragma unroll
        for (int j = 0; j < 4; j++) {
            float vvv = acc[i][j] + bv[j];
            if (relu) vvv = fmaxf(vvv, 0.f);
            Cb[(size_t)(m0 + ty*4 + i)*Nn + n0 + tx*4 + j] = vvv;
        }
    }
}

// ------------------- score path -------------------
__global__ void sp_kernel(const float* __restrict__ Wp) {
    __shared__ float wsh[H_];
    int t = threadIdx.x;                   // 256 threads
    if (t < H_) wsh[t] = Wp[t];
    __syncthreads();
    int lane = t & 31, w = t >> 5;
    int row = blockIdx.x * 8 + w;
    const float* hrow = g_h + (size_t)row * H_;
    float s = 0.f;
    #pragma unroll
    for (int c = lane; c < H_; c += 32) s += hrow[c] * wsh[c];
    #pragma unroll
    for (int o = 16; o; o >>= 1) s += __shfl_down_sync(0xffffffffu, s, o);
    if (lane == 0) g_sp[row] = s;
}

__global__ void score_agg_kernel(const float* __restrict__ bp) {
    int g = blockIdx.x;
    int t = threadIdx.x;                   // 256 threads, 8 warps
    int lane = t & 31, w = t >> 5;
    __shared__ float spsh[NP_];
    spsh[t] = g_sp[g*NP_ + t];
    __syncthreads();
    float bias0 = bp[0];
    for (int r = w; r < NP_; r += 8) {
        const float* row = g_A + ((size_t)g*NP_ + r)*NP_;
        float s = 0.f;
        #pragma unroll
        for (int c = lane; c < NP_; c += 32) s += row[c]*spsh[c];
        #pragma unroll
        for (int o = 16; o; o >>= 1) s += __shfl_down_sync(0xffffffffu, s, o);
        if (lane == 0) g_score[g*NP_ + r] = s + bias0;
    }
}

// ------------------- top-k (exact jax.lax.top_k order) + gather + tanh gate -------------------
__global__ void topk_kernel(int layer) {
    int g = blockIdx.x, t = threadIdx.x;   // 256 threads
    __shared__ float v[NP_];
    __shared__ int   ix[NP_];
    __shared__ float gate[DIMS_];
    v[t]  = g_score[g*NP_ + t];
    ix[t] = t;
    __syncthreads();
    // bitonic sort: descending by value, ascending index on ties
    for (int k = 2; k <= NP_; k <<= 1) {
        for (int j = k >> 1; j > 0; j >>= 1) {
            int p = t ^ j;
            if (p > t) {
                bool dirDesc = ((t & k) == 0);
                float v1 = v[t], v2 = v[p];
                int i1 = ix[t], i2 = ix[p];
                bool a_gt = (v1 > v2) || (v1 == v2 && i1 < i2);
                if (dirDesc != a_gt) {
                    v[t] = v2; v[p] = v1; ix[t] = i2; ix[p] = i1;
                }
            }
            __syncthreads();
        }
    }
    if (t < DIMS_) gate[t] = tanhf(v[t]);
    __syncthreads();
    float* dstp = g_feats + (size_t)(layer*B_ + g)*DIMS_*H_;
    for (int e = t; e < DIMS_*H_; e += 256) {
        int j = e >> 7, c = e & 127;
        dstp[e] = g_h[((size_t)g*NP_ + ix[j])*H_ + c] * gate[j];
    }
}

// ------------------- attention: one block per (graph, head), online softmax -------------------
__global__ void attn_kernel(int layer) {
    int bh = blockIdx.x;
    int b = bh >> 3, hd = bh & 7;
    int t = threadIdx.x;                   // 128 threads = query rows
    __shared__ float ksh[DIMS_][DK_];
    __shared__ float vsh[DIMS_][DK_];
    size_t base = (size_t)b * DIMS_ * H_;
    for (int e = t; e < DIMS_*DK_; e += 128) {
        int m = e >> 4, d = e & 15;
        ksh[m][d] = g_k[base + (size_t)m*H_ + hd*DK_ + d];
        vsh[m][d] = g_v[base + (size_t)m*H_ + hd*DK_ + d];
    }
    __syncthreads();
    float q[DK_];
    #pragma unroll
    for (int d = 0; d < DK_; d++) q[d] = g_q[base + (size_t)t*H_ + hd*DK_ + d];
    float mx = -INFINITY, sum = 0.f;
    float acc[DK_];
    #pragma unroll
    for (int d = 0; d < DK_; d++) acc[d] = 0.f;
    for (int m = 0; m < DIMS_; m++) {
        float s = 0.f;
        #pragma unroll
        for (int d = 0; d < DK_; d++) s += q[d]*ksh[m][d];
        s *= 0.25f;                        // 1/sqrt(16)
        float nm = fmaxf(mx, s);
        float corr = __expf(mx - nm);
        float p = __expf(s - nm);
        sum = sum*corr + p;
        #pragma unroll
        for (int d = 0; d < DK_; d++) acc[d] = acc[d]*corr + p*vsh[m][d];
        mx = nm;
    }
    float inv = 1.f / sum;
    float* ob = g_feats + (size_t)(layer*B_ + b)*DIMS_*H_ + (size_t)t*H_ + hd*DK_;
    #pragma unroll
    for (int d = 0; d < DK_; d++) ob[d] = acc[d]*inv;
}

// ------------------- fused classifier head: one block per graph -------------------
__global__ void head_kernel(const float* __restrict__ Wc1, const float* __restrict__ bc1,
                            const float* __restrict__ Wc2, const float* __restrict__ bc2,
                            const float* __restrict__ Wl1, const float* __restrict__ bl1,
                            const float* __restrict__ Wl2, const float* __restrict__ bl2,
                            float* __restrict__ out)
{
    int b = blockIdx.x;
    int t = threadIdx.x;                   // 128 threads
    __shared__ float ysh[C1_][H_];         // 16 KB
    __shared__ float ypsh[C1_][H_/2];      // 8 KB
    __shared__ float partial[128];
    __shared__ float z0[C2_];
    __shared__ float z1s[C2_];
    __shared__ float vv[NC_];

    // conv1: y[o][w] = relu(sum_{c,d} feats[c][b][d][w] * Wc1[o][c*128+d] + bc1[o])
    float acc[C1_];
    #pragma unroll
    for (int o = 0; o < C1_; o++) acc[o] = 0.f;
    for (int c = 0; c < 3; c++) {
        const float* fb = g_feats + (size_t)(c*B_ + b)*DIMS_*H_;
        for (int d = 0; d < DIMS_; d++) {
            float xv = fb[(size_t)d*H_ + t];
            int cd = c*DIMS_ + d;
            #pragma unroll
            for (int o = 0; o < C1_; o++) acc[o] += Wc1[o*384 + cd] * xv;
        }
    }
    #pragma unroll
    for (int o = 0; o < C1_; o++) ysh[o][t] = fmaxf(acc[o] + bc1[o], 0.f);
    __syncthreads();

    // maxpool (1,2)
    if (t < H_/2) {
        #pragma unroll
        for (int o = 0; o < C1_; o++)
            ypsh[o][t] = fmaxf(ysh[o][2*t], ysh[o][2*t+1]);
    }
    __syncthreads();

    // conv2: z[o2] = relu(sum_{c,w} yp[c][w]*Wc2[o2][c][w] + bc2[o2]); split across 2 half-threads
    {
        int o2 = t & 63, half = t >> 6;
        float s2 = 0.f;
        for (int c = half*16; c < half*16 + 16; c++) {
            const float* wrow = Wc2 + ((size_t)o2*C1_ + c)*64;
            #pragma unroll
            for (int w = 0; w < 64; w++) s2 += ypsh[c][w] * wrow[w];
        }
        partial[t] = s2;
    }
    __syncthreads();
    if (t < C2_) z0[t] = fmaxf(partial[t] + partial[t+64] + bc2[t], 0.f);
    __syncthreads();

    // linear1 (64->64) + relu
    if (t < C2_) {
        float s = bl1[t];
        #pragma unroll
        for (int i = 0; i < C2_; i++) s += z0[i] * Wl1[i*C2_ + t];
        z1s[t] = fmaxf(s, 0.f);
    }
    __syncthreads();

    // linear2 (64->10)
    if (t < NC_) {
        float s = bl2[t];
        #pragma unroll
        for (int i = 0; i < C2_; i++) s += z1s[i] * Wl2[i*NC_ + t];
        vv[t] = s;
    }
    __syncthreads();

    // log_softmax
    if (t == 0) {
        float mx = vv[0];
        for (int i = 1; i < NC_; i++) mx = fmaxf(mx, vv[i]);
        float se = 0.f;
        for (int i = 0; i < NC_; i++) se += expf(vv[i] - mx);
        float ls = logf(se);
        for (int i = 0; i < NC_; i++) out[b*NC_ + i] = vv[i] - mx - ls;
    }
}

// ------------------- host driver -------------------
extern "C" void kernel_launch(void* const* d_in, const int* in_sizes, int n_in,
                              void* d_out, int out_size)
{
    const float* x   = (const float*)d_in[0];
    const int*   src = (const int*)d_in[1];
    const int*   dst = (const int*)d_in[2];
    const float* Wg[3] = {(const float*)d_in[3], (const float*)d_in[5], (const float*)d_in[7]};
    const float* bg[3] = {(const float*)d_in[4], (const float*)d_in[6], (const float*)d_in[8]};
    const float* Wp  = (const float*)d_in[9];
    const float* bp  = (const float*)d_in[10];
    const float* Wq  = (const float*)d_in[11];
    const float* Wk  = (const float*)d_in[12];
    const float* Wv  = (const float*)d_in[13];
    const float* Wc1 = (const float*)d_in[14];
    const float* bc1 = (const float*)d_in[15];
    const float* Wc2 = (const float*)d_in[16];
    const float* bc2 = (const float*)d_in[17];
    const float* Wl1 = (const float*)d_in[18];
    const float* bl1 = (const float*)d_in[19];
    const float* Wl2 = (const float*)d_in[20];
    const float* bl2 = (const float*)d_in[21];
    int E = in_sizes[1];

    float *pA, *ppre, *ph, *pq, *pk, *pv, *pfeats;
    cudaGetSymbolAddress((void**)&pA,     g_A);
    cudaGetSymbolAddress((void**)&ppre,   g_pre);
    cudaGetSymbolAddress((void**)&ph,     g_h);
    cudaGetSymbolAddress((void**)&pq,     g_q);
    cudaGetSymbolAddress((void**)&pk,     g_k);
    cudaGetSymbolAddress((void**)&pv,     g_v);
    cudaGetSymbolAddress((void**)&pfeats, g_feats);

    size_t nA = (size_t)B_*NP_*NP_;
    zero_kernel<<<(int)((nA + 255)/256), 256>>>();
    deg_kernel<<<(E + 255)/256, 256>>>(dst, E);
    dnorm_kernel<<<(NN + 255)/256, 256>>>();
    buildA_kernel<<<(E + 255)/256, 256>>>(src, dst, E);

    for (int l = 0; l < 3; l++) {
        const float* hin = (l == 0) ? x : ph;
        // pre = h_in @ W_g[l]   (32768 x 128 x 128)
        gemm_kernel<<<dim3(NN/64, 2, 1), 256>>>(hin, Wg[l], nullptr, ppre,
                                                NN, H_, H_, 0, 0, 0, 0);
        // h = relu(A_hat @ pre + b)  batched per graph (256 x 128, K=256)
        gemm_kernel<<<dim3(NP_/64, 2, B_), 256>>>(pA, ppre, bg[l], ph,
                                                  NP_, H_, NP_,
                                                  (long long)NP_*NP_, (long long)NP_*H_,
                                                  (long long)NP_*H_, 1);
        // score pre: sp = h @ W_p
        sp_kernel<<<NN/8, 256>>>(Wp);
        // score = A_hat @ sp + b_p
        score_agg_kernel<<<B_, 256>>>(bp);
        // exact top-k + gather + tanh gate -> feats[l]
        topk_kernel<<<B_, 256>>>(l);
        // q,k,v projections (flat 16384 x 128 x 128)
        const float* fl = pfeats + (size_t)l*B_*DIMS_*H_;
        gemm_kernel<<<dim3(B_*DIMS_/64, 2, 1), 256>>>(fl, Wq, nullptr, pq,
                                                      B_*DIMS_, H_, H_, 0, 0, 0, 0);
        gemm_kernel<<<dim3(B_*DIMS_/64, 2, 1), 256>>>(fl, Wk, nullptr, pk,
                                                      B_*DIMS_, H_, H_, 0, 0, 0, 0);
        gemm_kernel<<<dim3(B_*DIMS_/64, 2, 1), 256>>>(fl, Wv, nullptr, pv,
                                                      B_*DIMS_, H_, H_, 0, 0, 0, 0);
        // attention, writes back into feats[l]
        attn_kernel<<<B_*HEADS_, 128>>>(l);
    }

    head_kernel<<<B_, 128>>>(Wc1, bc1, Wc2, bc2, Wl1, bl1, Wl2, bl2, (float*)d_out);
}

// round 2
// speedup vs baseline: 1.2046x; 1.2046x over previous
#include <cuda_runtime.h>
#include <math.h>

#define B_    128
#define NP_   256
#define NN    (B_*NP_)       // 32768
#define H_    128
#define DIMS_ 128
#define HEADS_ 8
#define DK_   16
#define C1_   32
#define C2_   64
#define NC_   10
#define EPG   4096           // symmetric edges per graph (2*2048)
#define ETOT  (B_*EPG)       // 524288

// ------------------- device scratch -------------------
__device__ float g_deg[NN];
__device__ float g_dnorm[NN];
__device__ int   g_off[NN];
__device__ int   g_cur[NN];
__device__ unsigned short g_csr[ETOT];
__device__ float g_pre[(size_t)NN*H_];
__device__ float g_h[(size_t)NN*H_];
__device__ float g_sp[NN];
__device__ float g_feats[(size_t)3*B_*DIMS_*H_];
__device__ float g_qkv[(size_t)B_*DIMS_*384];
__device__ float g_Wqkv[(size_t)H_*384];

// ------------------- prep -------------------
__global__ void zero_kernel() {
    int i = blockIdx.x * blockDim.x + threadIdx.x;
    if (i < NN) { g_deg[i] = 0.f; g_cur[i] = 0; }
}

__global__ void deg_kernel(const int* __restrict__ dst, int E) {
    int e = blockIdx.x * blockDim.x + threadIdx.x;
    if (e < E) atomicAdd(&g_deg[dst[e]], 1.0f);
}

__global__ void dnorm_kernel() {
    int i = blockIdx.x * blockDim.x + threadIdx.x;
    if (i < NN) g_dnorm[i] = rsqrtf(fmaxf(g_deg[i], 1.0f));
}

// per-graph exclusive scan of degrees -> CSR offsets (graph base = g*EPG)
__global__ void scan_kernel() {
    int g = blockIdx.x, t = threadIdx.x;    // 256 threads
    __shared__ int a[NP_];
    int node = g*NP_ + t;
    int v = (int)g_deg[node];
    a[t] = v;
    __syncthreads();
    for (int off = 1; off < NP_; off <<= 1) {
        int x = a[t];
        if (t >= off) x += a[t - off];
        __syncthreads();
        a[t] = x;
        __syncthreads();
    }
    g_off[node] = g*EPG + a[t] - v;         // exclusive
}

__global__ void scatter_kernel(const int* __restrict__ src, const int* __restrict__ dst, int E) {
    int e = blockIdx.x * blockDim.x + threadIdx.x;
    if (e < E) {
        int s = src[e], d = dst[e];
        int pos = atomicAdd(&g_cur[d], 1);
        g_csr[g_off[d] + pos] = (unsigned short)(s & 255);
    }
}

__global__ void packw_kernel(const float* __restrict__ Wq, const float* __restrict__ Wk,
                             const float* __restrict__ Wv) {
    int i = blockIdx.x * blockDim.x + threadIdx.x;
    if (i < H_*H_) {
        int k = i >> 7, c = i & 127;
        g_Wqkv[k*384 + c]       = Wq[i];
        g_Wqkv[k*384 + 128 + c] = Wk[i];
        g_Wqkv[k*384 + 256 + c] = Wv[i];
    }
}

// ------------------- fp32 SGEMM: C = A(MxK) @ B(KxN), 128x128 tile, 8x8/thread -------------------
__global__ void gemm128(const float* __restrict__ A, const float* __restrict__ B,
                        float* __restrict__ C, int M, int Nn, int K)
{
    __shared__ float As[8][128];
    __shared__ float Bs[8][128];
    int t = threadIdx.x;                    // 256
    int m0 = blockIdx.x * 128, n0 = blockIdx.y * 128;
    int tx = t & 15, ty = t >> 4;
    int arow = t >> 1, aseg = t & 1;
    int brow = t >> 5, bcol = t & 31;
    float acc[8][8];
    #pragma unroll
    for (int i = 0; i < 8; i++)
        #pragma unroll
        for (int j = 0; j < 8; j++) acc[i][j] = 0.f;

    for (int k0 = 0; k0 < K; k0 += 8) {
        float4 av  = *(const float4*)(A + (size_t)(m0 + arow)*K + k0 + aseg*4);
        float4 bvv = *(const float4*)(B + (size_t)(k0 + brow)*Nn + n0 + bcol*4);
        As[aseg*4+0][arow] = av.x;
        As[aseg*4+1][arow] = av.y;
        As[aseg*4+2][arow] = av.z;
        As[aseg*4+3][arow] = av.w;
        *(float4*)&Bs[brow][bcol*4] = bvv;
        __syncthreads();
        #pragma unroll
        for (int k = 0; k < 8; k++) {
            float a[8], bb[8];
            *(float4*)(a)    = *(float4*)&As[k][ty*8];
            *(float4*)(a+4)  = *(float4*)&As[k][ty*8+4];
            *(float4*)(bb)   = *(float4*)&Bs[k][tx*8];
            *(float4*)(bb+4) = *(float4*)&Bs[k][tx*8+4];
            #pragma unroll
            for (int i = 0; i < 8; i++)
                #pragma unroll
                for (int j = 0; j < 8; j++) acc[i][j] += a[i]*bb[j];
        }
        __syncthreads();
    }
    #pragma unroll
    for (int i = 0; i < 8; i++) {
        float* cp = C + (size_t)(m0 + ty*8 + i)*Nn + n0 + tx*8;
        float4 v0 = make_float4(acc[i][0], acc[i][1], acc[i][2], acc[i][3]);
        float4 v1 = make_float4(acc[i][4], acc[i][5], acc[i][6], acc[i][7]);
        *(float4*)cp     = v0;
        *(float4*)(cp+4) = v1;
    }
}

// ------------------- sparse aggregation: h = relu(dnorm_d * sum_e dnorm_s*pre[s] + b) -------------------
__global__ void agg_kernel(const float* __restrict__ pre, const float* __restrict__ bias,
                           float* __restrict__ hout)
{
    int g = blockIdx.x, t = threadIdx.x;    // 256 threads
    extern __shared__ float4 sh4[];         // [256][32] float4 = 128 KB
    const float4* pre4 = (const float4*)(pre + (size_t)g*NP_*H_);
    for (int i = t; i < NP_*32; i += 256) {
        int row = i >> 5;
        float sc = g_dnorm[g*NP_ + row];
        float4 v = pre4[i];
        v.x *= sc; v.y *= sc; v.z *= sc; v.w *= sc;
        sh4[i] = v;
    }
    __syncthreads();
    int warp = t >> 5, lane = t & 31;
    float4 bv = ((const float4*)bias)[lane];
    for (int d0 = warp*32; d0 < warp*32 + 32; d0 += 4) {
        int beg[4], len[4];
        float4 acc[4];
        int maxlen = 0;
        #pragma unroll
        for (int j = 0; j < 4; j++) {
            int node = g*NP_ + d0 + j;
            beg[j] = g_off[node];
            len[j] = (int)g_deg[node];
            maxlen = max(maxlen, len[j]);
            acc[j] = make_float4(0.f, 0.f, 0.f, 0.f);
        }
        for (int i = 0; i < maxlen; i++) {
            #pragma unroll
            for (int j = 0; j < 4; j++) {
                if (i < len[j]) {
                    int s = g_csr[beg[j] + i];
                    float4 v = sh4[s*32 + lane];
                    acc[j].x += v.x; acc[j].y += v.y; acc[j].z += v.z; acc[j].w += v.w;
                }
            }
        }
        #pragma unroll
        for (int j = 0; j < 4; j++) {
            int node = g*NP_ + d0 + j;
            float sc = g_dnorm[node];
            float4 o;
            o.x = fmaxf(acc[j].x*sc + bv.x, 0.f);
            o.y = fmaxf(acc[j].y*sc + bv.y, 0.f);
            o.z = fmaxf(acc[j].z*sc + bv.z, 0.f);
            o.w = fmaxf(acc[j].w*sc + bv.w, 0.f);
            ((float4*)hout)[(size_t)node*32 + lane] = o;
        }
    }
}

// ------------------- score pre: sp = h @ W_p -------------------
__global__ void sp_kernel(const float* __restrict__ Wp) {
    __shared__ float wsh[H_];
    int t = threadIdx.x;                    // 256 threads
    if (t < H_) wsh[t] = Wp[t];
    __syncthreads();
    int lane = t & 31, w = t >> 5;
    int row = blockIdx.x * 8 + w;
    const float* hrow = g_h + (size_t)row * H_;
    float s = 0.f;
    #pragma unroll
    for (int c = lane; c < H_; c += 32) s += hrow[c] * wsh[c];
    #pragma unroll
    for (int o = 16; o; o >>= 1) s += __shfl_down_sync(0xffffffffu, s, o);
    if (lane == 0) g_sp[row] = s;
}

// ------------------- score (CSR) + exact top-k + gather + tanh gate -------------------
__global__ void topk_kernel(const float* __restrict__ bp, int layer) {
    int g = blockIdx.x, t = threadIdx.x;    // 256 threads
    __shared__ float ssh[NP_];
    __shared__ float v[NP_];
    __shared__ int   ix[NP_];
    __shared__ float gate[DIMS_];
    int node = g*NP_ + t;
    ssh[t] = g_sp[node] * g_dnorm[node];
    __syncthreads();
    {
        int beg = g_off[node], len = (int)g_deg[node];
        float s = 0.f;
        for (int i = 0; i < len; i++) s += ssh[g_csr[beg + i]];
        v[t]  = s * g_dnorm[node] + bp[0];
        ix[t] = t;
    }
    __syncthreads();
    // bitonic sort: descending value, ascending index on ties (jax.lax.top_k order)
    for (int k = 2; k <= NP_; k <<= 1) {
        for (int j = k >> 1; j > 0; j >>= 1) {
            int p = t ^ j;
            if (p > t) {
                bool dirDesc = ((t & k) == 0);
                float v1 = v[t], v2 = v[p];
                int i1 = ix[t], i2 = ix[p];
                bool a_gt = (v1 > v2) || (v1 == v2 && i1 < i2);
                if (dirDesc != a_gt) {
                    v[t] = v2; v[p] = v1; ix[t] = i2; ix[p] = i1;
                }
            }
            __syncthreads();
        }
    }
    if (t < DIMS_) gate[t] = tanhf(v[t]);
    __syncthreads();
    float* dstp = g_feats + (size_t)(layer*B_ + g)*DIMS_*H_;
    for (int e = t; e < DIMS_*H_; e += 256) {
        int j = e >> 7, c = e & 127;
        dstp[e] = g_h[((size_t)g*NP_ + ix[j])*H_ + c] * gate[j];
    }
}

// ------------------- attention (online softmax), qkv packed [row][384] -------------------
__global__ void attn_kernel(int layer) {
    int bh = blockIdx.x;
    int b = bh >> 3, hd = bh & 7;
    int t = threadIdx.x;                    // 128 threads = query rows
    __shared__ float ksh[DIMS_][DK_];
    __shared__ float vsh[DIMS_][DK_];
    const float* qkv = g_qkv + (size_t)b * DIMS_ * 384;
    for (int e = t; e < DIMS_*DK_; e += 128) {
        int m = e >> 4, d = e & 15;
        ksh[m][d] = qkv[(size_t)m*384 + 128 + hd*DK_ + d];
        vsh[m][d] = qkv[(size_t)m*384 + 256 + hd*DK_ + d];
    }
    __syncthreads();
    float q[DK_];
    #pragma unroll
    for (int d = 0; d < DK_; d++) q[d] = qkv[(size_t)t*384 + hd*DK_ + d];
    float mx = -INFINITY, sum = 0.f;
    float acc[DK_];
    #pragma unroll
    for (int d = 0; d < DK_; d++) acc[d] = 0.f;
    for (int m = 0; m < DIMS_; m++) {
        float s = 0.f;
        #pragma unroll
        for (int d = 0; d < DK_; d++) s += q[d]*ksh[m][d];
        s *= 0.25f;
        float nm = fmaxf(mx, s);
        float corr = __expf(mx - nm);
        float p = __expf(s - nm);
        sum = sum*corr + p;
        #pragma unroll
        for (int d = 0; d < DK_; d++) acc[d] = acc[d]*corr + p*vsh[m][d];
        mx = nm;
    }
    float inv = 1.f / sum;
    float* ob = g_feats + (size_t)(layer*B_ + b)*DIMS_*H_ + (size_t)t*H_ + hd*DK_;
    #pragma unroll
    for (int d = 0; d < DK_; d++) ob[d] = acc[d]*inv;
}

// ------------------- fused classifier head -------------------
__global__ void head_kernel(const float* __restrict__ Wc1, const float* __restrict__ bc1,
                            const float* __restrict__ Wc2, const float* __restrict__ bc2,
                            const float* __restrict__ Wl1, const float* __restrict__ bl1,
                            const float* __restrict__ Wl2, const float* __restrict__ bl2,
                            float* __restrict__ out)
{
    int b = blockIdx.x;
    int t = threadIdx.x;                    // 128 threads
    __shared__ float ysh[C1_][H_];
    __shared__ float ypsh[C1_][H_/2];
    __shared__ float partial[128];
    __shared__ float z0[C2_];
    __shared__ float z1s[C2_];
    __shared__ float vv[NC_];

    float acc[C1_];
    #pragma unroll
    for (int o = 0; o < C1_; o++) acc[o] = 0.f;
    for (int c = 0; c < 3; c++) {
        const float* fb = g_feats + (size_t)(c*B_ + b)*DIMS_*H_;
        for (int d = 0; d < DIMS_; d++) {
            float xv = fb[(size_t)d*H_ + t];
            int cd = c*DIMS_ + d;
            #pragma unroll
            for (int o = 0; o < C1_; o++) acc[o] += Wc1[o*384 + cd] * xv;
        }
    }
    #pragma unroll
    for (int o = 0; o < C1_; o++) ysh[o][t] = fmaxf(acc[o] + bc1[o], 0.f);
    __syncthreads();

    if (t < H_/2) {
        #pragma unroll
        for (int o = 0; o < C1_; o++)
            ypsh[o][t] = fmaxf(ysh[o][2*t], ysh[o][2*t+1]);
    }
    __syncthreads();

    {
        int o2 = t & 63, half = t >> 6;
        float s2 = 0.f;
        for (int c = half*16; c < half*16 + 16; c++) {
            const float* wrow = Wc2 + ((size_t)o2*C1_ + c)*64;
            #pragma unroll
            for (int w = 0; w < 64; w++) s2 += ypsh[c][w] * wrow[w];
        }
        partial[t] = s2;
    }
    __syncthreads();
    if (t < C2_) z0[t] = fmaxf(partial[t] + partial[t+64] + bc2[t], 0.f);
    __syncthreads();

    if (t < C2_) {
        float s = bl1[t];
        #pragma unroll
        for (int i = 0; i < C2_; i++) s += z0[i] * Wl1[i*C2_ + t];
        z1s[t] = fmaxf(s, 0.f);
    }
    __syncthreads();

    if (t < NC_) {
        float s = bl2[t];
        #pragma unroll
        for (int i = 0; i < C2_; i++) s += z1s[i] * Wl2[i*NC_ + t];
        vv[t] = s;
    }
    __syncthreads();

    if (t == 0) {
        float mx = vv[0];
        for (int i = 1; i < NC_; i++) mx = fmaxf(mx, vv[i]);
        float se = 0.f;
        for (int i = 0; i < NC_; i++) se += expf(vv[i] - mx);
        float ls = logf(se);
        for (int i = 0; i < NC_; i++) out[b*NC_ + i] = vv[i] - mx - ls;
    }
}

// ------------------- host driver -------------------
extern "C" void kernel_launch(void* const* d_in, const int* in_sizes, int n_in,
                              void* d_out, int out_size)
{
    const float* x   = (const float*)d_in[0];
    const int*   src = (const int*)d_in[1];
    const int*   dst = (const int*)d_in[2];
    const float* Wg[3] = {(const float*)d_in[3], (const float*)d_in[5], (const float*)d_in[7]};
    const float* bg[3] = {(const float*)d_in[4], (const float*)d_in[6], (const float*)d_in[8]};
    const float* Wp  = (const float*)d_in[9];
    const float* bp  = (const float*)d_in[10];
    const float* Wq  = (const float*)d_in[11];
    const float* Wk  = (const float*)d_in[12];
    const float* Wv  = (const float*)d_in[13];
    const float* Wc1 = (const float*)d_in[14];
    const float* bc1 = (const float*)d_in[15];
    const float* Wc2 = (const float*)d_in[16];
    const float* bc2 = (const float*)d_in[17];
    const float* Wl1 = (const float*)d_in[18];
    const float* bl1 = (const float*)d_in[19];
    const float* Wl2 = (const float*)d_in[20];
    const float* bl2 = (const float*)d_in[21];
    int E = in_sizes[1];

    float *ppre, *ph, *pqkv, *pfeats, *pWqkv;
    cudaGetSymbolAddress((void**)&ppre,   g_pre);
    cudaGetSymbolAddress((void**)&ph,     g_h);
    cudaGetSymbolAddress((void**)&pqkv,   g_qkv);
    cudaGetSymbolAddress((void**)&pfeats, g_feats);
    cudaGetSymbolAddress((void**)&pWqkv,  g_Wqkv);

    const int AGG_SMEM = NP_ * 32 * (int)sizeof(float4);   // 128 KB
    cudaFuncSetAttribute(agg_kernel, cudaFuncAttributeMaxDynamicSharedMemorySize, AGG_SMEM);

    zero_kernel<<<(NN + 255)/256, 256>>>();
    deg_kernel<<<(E + 255)/256, 256>>>(dst, E);
    dnorm_kernel<<<(NN + 255)/256, 256>>>();
    scan_kernel<<<B_, NP_>>>();
    scatter_kernel<<<(E + 255)/256, 256>>>(src, dst, E);
    packw_kernel<<<(H_*H_ + 255)/256, 256>>>(Wq, Wk, Wv);

    for (int l = 0; l < 3; l++) {
        const float* hin = (l == 0) ? x : ph;
        // pre = h_in @ W_g[l]  (32768 x 128 x 128)
        gemm128<<<dim3(NN/128, 1), 256>>>(hin, Wg[l], ppre, NN, H_, H_);
        // h = relu(D^-1/2 A D^-1/2 pre + b) via CSR + smem-staged tile
        agg_kernel<<<B_, 256, AGG_SMEM>>>(ppre, bg[l], ph);
        // sp = h @ W_p
        sp_kernel<<<NN/8, 256>>>(Wp);
        // score (CSR) + top-k + gather + gate
        topk_kernel<<<B_, NP_>>>(bp, l);
        // qkv = feats_l @ [Wq|Wk|Wv]  (16384 x 384 x 128)
        const float* fl = pfeats + (size_t)l*B_*DIMS_*H_;
        gemm128<<<dim3(B_*DIMS_/128, 3), 256>>>(fl, pWqkv, pqkv, B_*DIMS_, 384, H_);
        // attention -> feats_l
        attn_kernel<<<B_*HEADS_, 128>>>(l);
    }

    head_kernel<<<B_, 128>>>(Wc1, bc1, Wc2, bc2, Wl1, bl1, Wl2, bl2, (float*)d_out);
}

// round 3
// speedup vs baseline: 1.2173x; 1.0105x over previous
#include <cuda_runtime.h>
#include <math.h>
#include <mma.h>
using namespace nvcuda;

#define B_    128
#define NP_   256
#define NN    (B_*NP_)
#define H_    128
#define DIMS_ 128
#define HEADS_ 8
#define DK_   16
#define C1_   32
#define C2_   64
#define NC_   10
#define EPG   4096
#define ETOT  (B_*EPG)

// ------------------- device scratch -------------------
__device__ float g_deg[NN];
__device__ float g_dnorm[NN];
__device__ int   g_off[NN];
__device__ int   g_cur[NN];
__device__ unsigned short g_csr[ETOT];
__device__ float g_pre[(size_t)NN*H_];
__device__ float g_h[(size_t)NN*H_];
__device__ float g_sp[NN];
__device__ float g_feats[(size_t)3*B_*DIMS_*H_];
__device__ float g_qkv[(size_t)B_*DIMS_*384];
__device__ float g_Wqkv[(size_t)H_*384];

// ------------------- prep -------------------
__global__ void zero_kernel() {
    int i = blockIdx.x * blockDim.x + threadIdx.x;
    if (i < NN) { g_deg[i] = 0.f; g_cur[i] = 0; }
}
__global__ void deg_kernel(const int* __restrict__ dst, int E) {
    int e = blockIdx.x * blockDim.x + threadIdx.x;
    if (e < E) atomicAdd(&g_deg[dst[e]], 1.0f);
}
__global__ void dnorm_kernel() {
    int i = blockIdx.x * blockDim.x + threadIdx.x;
    if (i < NN) g_dnorm[i] = rsqrtf(fmaxf(g_deg[i], 1.0f));
}
__global__ void scan_kernel() {
    int g = blockIdx.x, t = threadIdx.x;
    __shared__ int a[NP_];
    int node = g*NP_ + t;
    int v = (int)g_deg[node];
    a[t] = v;
    __syncthreads();
    for (int off = 1; off < NP_; off <<= 1) {
        int x = a[t];
        if (t >= off) x += a[t - off];
        __syncthreads();
        a[t] = x;
        __syncthreads();
    }
    g_off[node] = g*EPG + a[t] - v;
}
__global__ void scatter_kernel(const int* __restrict__ src, const int* __restrict__ dst, int E) {
    int e = blockIdx.x * blockDim.x + threadIdx.x;
    if (e < E) {
        int s = src[e], d = dst[e];
        int pos = atomicAdd(&g_cur[d], 1);
        g_csr[g_off[d] + pos] = (unsigned short)(s & 255);
    }
}
__global__ void packw_kernel(const float* __restrict__ Wq, const float* __restrict__ Wk,
                             const float* __restrict__ Wv) {
    int i = blockIdx.x * blockDim.x + threadIdx.x;
    if (i < H_*H_) {
        int k = i >> 7, c = i & 127;
        g_Wqkv[k*384 + c]       = Wq[i];
        g_Wqkv[k*384 + 128 + c] = Wk[i];
        g_Wqkv[k*384 + 256 + c] = Wv[i];
    }
}

// ------------------- fp32 SGEMM (score path: must stay exact fp32) -------------------
__global__ void gemm128(const float* __restrict__ A, const float* __restrict__ B,
                        float* __restrict__ C, int M, int Nn, int K)
{
    __shared__ float As[8][128];
    __shared__ float Bs[8][128];
    int t = threadIdx.x;
    int m0 = blockIdx.x * 128, n0 = blockIdx.y * 128;
    int tx = t & 15, ty = t >> 4;
    int arow = t >> 1, aseg = t & 1;
    int brow = t >> 5, bcol = t & 31;
    float acc[8][8];
    #pragma unroll
    for (int i = 0; i < 8; i++)
        #pragma unroll
        for (int j = 0; j < 8; j++) acc[i][j] = 0.f;

    for (int k0 = 0; k0 < K; k0 += 8) {
        float4 av  = *(const float4*)(A + (size_t)(m0 + arow)*K + k0 + aseg*4);
        float4 bvv = *(const float4*)(B + (size_t)(k0 + brow)*Nn + n0 + bcol*4);
        As[aseg*4+0][arow] = av.x;
        As[aseg*4+1][arow] = av.y;
        As[aseg*4+2][arow] = av.z;
        As[aseg*4+3][arow] = av.w;
        *(float4*)&Bs[brow][bcol*4] = bvv;
        __syncthreads();
        #pragma unroll
        for (int k = 0; k < 8; k++) {
            float a[8], bb[8];
            *(float4*)(a)    = *(float4*)&As[k][ty*8];
            *(float4*)(a+4)  = *(float4*)&As[k][ty*8+4];
            *(float4*)(bb)   = *(float4*)&Bs[k][tx*8];
            *(float4*)(bb+4) = *(float4*)&Bs[k][tx*8+4];
            #pragma unroll
            for (int i = 0; i < 8; i++)
                #pragma unroll
                for (int j = 0; j < 8; j++) acc[i][j] += a[i]*bb[j];
        }
        __syncthreads();
    }
    #pragma unroll
    for (int i = 0; i < 8; i++) {
        float* cp = C + (size_t)(m0 + ty*8 + i)*Nn + n0 + tx*8;
        *(float4*)cp     = make_float4(acc[i][0], acc[i][1], acc[i][2], acc[i][3]);
        *(float4*)(cp+4) = make_float4(acc[i][4], acc[i][5], acc[i][6], acc[i][7]);
    }
}

// ------------------- tf32 WMMA GEMM for QKV: C[M x 384] = A[M x 128] @ W[128 x 384] -------------------
__global__ void qkv_wmma(const float* __restrict__ A, const float* __restrict__ Bm,
                         float* __restrict__ C)
{
    extern __shared__ float qsm[];
    float* As = qsm;                 // [64][132]
    float* Bs = qsm + 64*132;        // [128][68]
    int m0 = blockIdx.x * 64, n0 = blockIdx.y * 64;
    int t = threadIdx.x;             // 128 threads, 4 warps

    for (int i = t; i < 64*32; i += 128) {
        int r = i >> 5, c = i & 31;
        *(float4*)&As[r*132 + c*4] = *(const float4*)(A + (size_t)(m0+r)*128 + c*4);
    }
    for (int i = t; i < 128*16; i += 128) {
        int r = i >> 4, c = i & 15;
        *(float4*)&Bs[r*68 + c*4] = *(const float4*)(Bm + (size_t)r*384 + n0 + c*4);
    }
    __syncthreads();

    int w = t >> 5;
    int wm = (w & 1) * 32, wn = (w >> 1) * 32;
    wmma::fragment<wmma::accumulator, 16, 16, 8, float> acc[2][2];
    #pragma unroll
    for (int i = 0; i < 2; i++)
        #pragma unroll
        for (int j = 0; j < 2; j++) wmma::fill_fragment(acc[i][j], 0.f);

    #pragma unroll
    for (int k = 0; k < 128; k += 8) {
        wmma::fragment<wmma::matrix_a, 16, 16, 8, wmma::precision::tf32, wmma::row_major> af[2];
        wmma::fragment<wmma::matrix_b, 16, 16, 8, wmma::precision::tf32, wmma::row_major> bf[2];
        #pragma unroll
        for (int i = 0; i < 2; i++) {
            wmma::load_matrix_sync(af[i], &As[(wm + i*16)*132 + k], 132);
            #pragma unroll
            for (int e = 0; e < af[i].num_elements; e++)
                af[i].x[e] = wmma::__float_to_tf32(af[i].x[e]);
        }
        #pragma unroll
        for (int j = 0; j < 2; j++) {
            wmma::load_matrix_sync(bf[j], &Bs[k*68 + wn + j*16], 68);
            #pragma unroll
            for (int e = 0; e < bf[j].num_elements; e++)
                bf[j].x[e] = wmma::__float_to_tf32(bf[j].x[e]);
        }
        #pragma unroll
        for (int i = 0; i < 2; i++)
            #pragma unroll
            for (int j = 0; j < 2; j++)
                wmma::mma_sync(acc[i][j], af[i], bf[j], acc[i][j]);
    }
    #pragma unroll
    for (int i = 0; i < 2; i++)
        #pragma unroll
        for (int j = 0; j < 2; j++)
            wmma::store_matrix_sync(C + (size_t)(m0 + wm + i*16)*384 + n0 + wn + j*16,
                                    acc[i][j], 384, wmma::mem_row_major);
}

// ------------------- sparse aggregation + fused score projection -------------------
__global__ void agg_kernel(const float* __restrict__ pre, const float* __restrict__ bias,
                           const float* __restrict__ Wp, float* __restrict__ hout)
{
    int g = blockIdx.x, t = threadIdx.x;    // 512 threads
    extern __shared__ float4 sh4[];         // [256][32] float4 = 128 KB
    const float4* pre4 = (const float4*)(pre + (size_t)g*NP_*H_);
    for (int i = t; i < NP_*32; i += 512) {
        int row = i >> 5;
        float sc = g_dnorm[g*NP_ + row];
        float4 v = pre4[i];
        v.x *= sc; v.y *= sc; v.z *= sc; v.w *= sc;
        sh4[i] = v;
    }
    __syncthreads();
    int warp = t >> 5, lane = t & 31;       // 16 warps, 16 dst nodes each
    float4 bv = ((const float4*)bias)[lane];
    float4 wp = ((const float4*)Wp)[lane];
    for (int d0 = warp*16; d0 < warp*16 + 16; d0 += 4) {
        int beg[4], len[4];
        float4 acc[4];
        int maxlen = 0;
        #pragma unroll
        for (int j = 0; j < 4; j++) {
            int node = g*NP_ + d0 + j;
            beg[j] = g_off[node];
            len[j] = (int)g_deg[node];
            maxlen = max(maxlen, len[j]);
            acc[j] = make_float4(0.f, 0.f, 0.f, 0.f);
        }
        for (int i = 0; i < maxlen; i++) {
            #pragma unroll
            for (int j = 0; j < 4; j++) {
                if (i < len[j]) {
                    int s = g_csr[beg[j] + i];
                    float4 v = sh4[s*32 + lane];
                    acc[j].x += v.x; acc[j].y += v.y; acc[j].z += v.z; acc[j].w += v.w;
                }
            }
        }
        #pragma unroll
        for (int j = 0; j < 4; j++) {
            int node = g*NP_ + d0 + j;
            float sc = g_dnorm[node];
            float4 o;
            o.x = fmaxf(acc[j].x*sc + bv.x, 0.f);
            o.y = fmaxf(acc[j].y*sc + bv.y, 0.f);
            o.z = fmaxf(acc[j].z*sc + bv.z, 0.f);
            o.w = fmaxf(acc[j].w*sc + bv.w, 0.f);
            ((float4*)hout)[(size_t)node*32 + lane] = o;
            // fused sp = h @ W_p (warp reduce across 32 lanes = 128 features)
            float s = o.x*wp.x + o.y*wp.y + o.z*wp.z + o.w*wp.w;
            #pragma unroll
            for (int off = 16; off; off >>= 1) s += __shfl_down_sync(0xffffffffu, s, off);
            if (lane == 0) g_sp[node] = s;
        }
    }
}

// ------------------- score (CSR) + exact top-k + gather + tanh gate -------------------
__global__ void topk_kernel(const float* __restrict__ bp, int layer) {
    int g = blockIdx.x, t = threadIdx.x;
    __shared__ float ssh[NP_];
    __shared__ float v[NP_];
    __shared__ int   ix[NP_];
    __shared__ float gate[DIMS_];
    int node = g*NP_ + t;
    ssh[t] = g_sp[node] * g_dnorm[node];
    __syncthreads();
    {
        int beg = g_off[node], len = (int)g_deg[node];
        float s = 0.f;
        for (int i = 0; i < len; i++) s += ssh[g_csr[beg + i]];
        v[t]  = s * g_dnorm[node] + bp[0];
        ix[t] = t;
    }
    __syncthreads();
    for (int k = 2; k <= NP_; k <<= 1) {
        for (int j = k >> 1; j > 0; j >>= 1) {
            int p = t ^ j;
            if (p > t) {
                bool dirDesc = ((t & k) == 0);
                float v1 = v[t], v2 = v[p];
                int i1 = ix[t], i2 = ix[p];
                bool a_gt = (v1 > v2) || (v1 == v2 && i1 < i2);
                if (dirDesc != a_gt) {
                    v[t] = v2; v[p] = v1; ix[t] = i2; ix[p] = i1;
                }
            }
            __syncthreads();
        }
    }
    if (t < DIMS_) gate[t] = tanhf(v[t]);
    __syncthreads();
    float* dstp = g_feats + (size_t)(layer*B_ + g)*DIMS_*H_;
    for (int e = t; e < DIMS_*H_; e += 256) {
        int j = e >> 7, c = e & 127;
        dstp[e] = g_h[((size_t)g*NP_ + ix[j])*H_ + c] * gate[j];
    }
}

// ------------------- fast exp on FMA pipe (no MUFU) -------------------
__device__ __forceinline__ float fast_exp(float x) {
    float y = x * 1.4426950408889634f;           // log2(e)
    if (y < -120.f) return 0.f;
    float n = rintf(y);
    float r = (y - n) * 0.6931471805599453f;     // back to natural units, |r| <= 0.3466
    float p = 1.f/720.f;
    p = p*r + 1.f/120.f;
    p = p*r + 1.f/24.f;
    p = p*r + 1.f/6.f;
    p = p*r + 0.5f;
    p = p*r + 1.f;
    p = p*r + 1.f;
    int e = (int)n;
    float s = __int_as_float((e + 127) << 23);
    return p * s;
}

// ------------------- attention: one block per (graph, head), smem scores -------------------
#define SSTR 129
__global__ void attn_kernel(int layer) {
    extern __shared__ float asm_[];
    float* ksh  = asm_;                    // [128][16]
    float* vsh  = asm_ + 2048;             // [128][16]
    float* S    = asm_ + 4096;             // [128][129]
    float* rsum = asm_ + 4096 + 128*SSTR;  // [128]

    int bh = blockIdx.x;
    int b = bh >> 3, hd = bh & 7;
    int t = threadIdx.x;                   // 256 threads
    const float* qkv = g_qkv + (size_t)b * DIMS_ * 384;

    for (int e = t; e < DIMS_*DK_; e += 256) {
        int m = e >> 4, d = e & 15;
        ksh[m*DK_ + d] = qkv[(size_t)m*384 + 128 + hd*DK_ + d];
        vsh[m*DK_ + d] = qkv[(size_t)m*384 + 256 + hd*DK_ + d];
    }
    __syncthreads();

    // Phase A: scores. thread -> (q = t>>1, half = t&1), 64 keys each.
    int q = t >> 1, half = t & 1;
    float qv[DK_];
    #pragma unroll
    for (int d = 0; d < DK_; d++) qv[d] = qkv[(size_t)q*384 + hd*DK_ + d];
    float lmax = -INFINITY;
    #pragma unroll 4
    for (int i = 0; i < 64; i++) {
        int m = half*64 + i;
        float s = 0.f;
        #pragma unroll
        for (int d = 0; d < DK_; d++) s += qv[d]*ksh[m*DK_ + d];
        s *= 0.25f;
        S[q*SSTR + m] = s;
        lmax = fmaxf(lmax, s);
    }
    float rmax = fmaxf(lmax, __shfl_xor_sync(0xffffffffu, lmax, 1));
    // Phase B: exp + row sum (same mapping; no barrier needed between A and B per-thread region)
    float lsum = 0.f;
    #pragma unroll 4
    for (int i = 0; i < 64; i++) {
        int m = half*64 + i;
        float p = fast_exp(S[q*SSTR + m] - rmax);
        S[q*SSTR + m] = p;
        lsum += p;
    }
    lsum += __shfl_xor_sync(0xffffffffu, lsum, 1);
    if (half == 0) rsum[q] = lsum;
    __syncthreads();

    // Phase C: O = P @ V. thread -> (q = t&127, dhalf = t>>7), 8 dims each.
    int q2 = t & 127, dh = t >> 7;
    float acc[8];
    #pragma unroll
    for (int j = 0; j < 8; j++) acc[j] = 0.f;
    for (int m = 0; m < 128; m++) {
        float p = S[q2*SSTR + m];
        #pragma unroll
        for (int j = 0; j < 8; j++) acc[j] += p * vsh[m*DK_ + dh*8 + j];
    }
    float inv = 1.f / rsum[q2];
    float* ob = g_feats + (size_t)(layer*B_ + b)*DIMS_*H_ + (size_t)q2*H_ + hd*DK_ + dh*8;
    *(float4*)ob     = make_float4(acc[0]*inv, acc[1]*inv, acc[2]*inv, acc[3]*inv);
    *(float4*)(ob+4) = make_float4(acc[4]*inv, acc[5]*inv, acc[6]*inv, acc[7]*inv);
}

// ------------------- fused classifier head -------------------
__global__ void head_kernel(const float* __restrict__ Wc1, const float* __restrict__ bc1,
                            const float* __restrict__ Wc2, const float* __restrict__ bc2,
                            const float* __restrict__ Wl1, const float* __restrict__ bl1,
                            const float* __restrict__ Wl2, const float* __restrict__ bl2,
                            float* __restrict__ out)
{
    int b = blockIdx.x;
    int t = threadIdx.x;
    __shared__ float ysh[C1_][H_];
    __shared__ float ypsh[C1_][H_/2];
    __shared__ float partial[128];
    __shared__ float z0[C2_];
    __shared__ float z1s[C2_];
    __shared__ float vv[NC_];

    float acc[C1_];
    #pragma unroll
    for (int o = 0; o < C1_; o++) acc[o] = 0.f;
    for (int c = 0; c < 3; c++) {
        const float* fb = g_feats + (size_t)(c*B_ + b)*DIMS_*H_;
        for (int d = 0; d < DIMS_; d++) {
            float xv = fb[(size_t)d*H_ + t];
            int cd = c*DIMS_ + d;
            #pragma unroll
            for (int o = 0; o < C1_; o++) acc[o] += Wc1[o*384 + cd] * xv;
        }
    }
    #pragma unroll
    for (int o = 0; o < C1_; o++) ysh[o][t] = fmaxf(acc[o] + bc1[o], 0.f);
    __syncthreads();

    if (t < H_/2) {
        #pragma unroll
        for (int o = 0; o < C1_; o++)
            ypsh[o][t] = fmaxf(ysh[o][2*t], ysh[o][2*t+1]);
    }
    __syncthreads();

    {
        int o2 = t & 63, halfq = t >> 6;
        float s2 = 0.f;
        for (int c = halfq*16; c < halfq*16 + 16; c++) {
            const float* wrow = Wc2 + ((size_t)o2*C1_ + c)*64;
            #pragma unroll
            for (int w = 0; w < 64; w++) s2 += ypsh[c][w] * wrow[w];
        }
        partial[t] = s2;
    }
    __syncthreads();
    if (t < C2_) z0[t] = fmaxf(partial[t] + partial[t+64] + bc2[t], 0.f);
    __syncthreads();

    if (t < C2_) {
        float s = bl1[t];
        #pragma unroll
        for (int i = 0; i < C2_; i++) s += z0[i] * Wl1[i*C2_ + t];
        z1s[t] = fmaxf(s, 0.f);
    }
    __syncthreads();

    if (t < NC_) {
        float s = bl2[t];
        #pragma unroll
        for (int i = 0; i < C2_; i++) s += z1s[i] * Wl2[i*NC_ + t];
        vv[t] = s;
    }
    __syncthreads();

    if (t == 0) {
        float mx = vv[0];
        for (int i = 1; i < NC_; i++) mx = fmaxf(mx, vv[i]);
        float se = 0.f;
        for (int i = 0; i < NC_; i++) se += expf(vv[i] - mx);
        float ls = logf(se);
        for (int i = 0; i < NC_; i++) out[b*NC_ + i] = vv[i] - mx - ls;
    }
}

// ------------------- host driver -------------------
extern "C" void kernel_launch(void* const* d_in, const int* in_sizes, int n_in,
                              void* d_out, int out_size)
{
    const float* x   = (const float*)d_in[0];
    const int*   src = (const int*)d_in[1];
    const int*   dst = (const int*)d_in[2];
    const float* Wg[3] = {(const float*)d_in[3], (const float*)d_in[5], (const float*)d_in[7]};
    const float* bg[3] = {(const float*)d_in[4], (const float*)d_in[6], (const float*)d_in[8]};
    const float* Wp  = (const float*)d_in[9];
    const float* bp  = (const float*)d_in[10];
    const float* Wq  = (const float*)d_in[11];
    const float* Wk  = (const float*)d_in[12];
    const float* Wv  = (const float*)d_in[13];
    const float* Wc1 = (const float*)d_in[14];
    const float* bc1 = (const float*)d_in[15];
    const float* Wc2 = (const float*)d_in[16];
    const float* bc2 = (const float*)d_in[17];
    const float* Wl1 = (const float*)d_in[18];
    const float* bl1 = (const float*)d_in[19];
    const float* Wl2 = (const float*)d_in[20];
    const float* bl2 = (const float*)d_in[21];
    int E = in_sizes[1];

    float *ppre, *ph, *pqkv, *pfeats, *pWqkv;
    cudaGetSymbolAddress((void**)&ppre,   g_pre);
    cudaGetSymbolAddress((void**)&ph,     g_h);
    cudaGetSymbolAddress((void**)&pqkv,   g_qkv);
    cudaGetSymbolAddress((void**)&pfeats, g_feats);
    cudaGetSymbolAddress((void**)&pWqkv,  g_Wqkv);

    const int AGG_SMEM  = NP_ * 32 * (int)sizeof(float4);            // 128 KB
    const int QKV_SMEM  = (64*132 + 128*68) * (int)sizeof(float);    // 68.6 KB
    const int ATTN_SMEM = (4096 + 128*SSTR + 128) * (int)sizeof(float); // ~83 KB
    cudaFuncSetAttribute(agg_kernel,  cudaFuncAttributeMaxDynamicSharedMemorySize, AGG_SMEM);
    cudaFuncSetAttribute(qkv_wmma,    cudaFuncAttributeMaxDynamicSharedMemorySize, QKV_SMEM);
    cudaFuncSetAttribute(attn_kernel, cudaFuncAttributeMaxDynamicSharedMemorySize, ATTN_SMEM);

    zero_kernel<<<(NN + 255)/256, 256>>>();
    deg_kernel<<<(E + 255)/256, 256>>>(dst, E);
    dnorm_kernel<<<(NN + 255)/256, 256>>>();
    scan_kernel<<<B_, NP_>>>();
    scatter_kernel<<<(E + 255)/256, 256>>>(src, dst, E);
    packw_kernel<<<(H_*H_ + 255)/256, 256>>>(Wq, Wk, Wv);

    for (int l = 0; l < 3; l++) {
        const float* hin = (l == 0) ? x : ph;
        // pre = h_in @ W_g[l]  (exact fp32 — feeds top-k ordering)
        gemm128<<<dim3(NN/128, 1), 256>>>(hin, Wg[l], ppre, NN, H_, H_);
        // h = relu(D^-1/2 A D^-1/2 pre + b) + fused sp = h @ W_p
        agg_kernel<<<B_, 512, AGG_SMEM>>>(ppre, bg[l], Wp, ph);
        // score (CSR) + top-k + gather + gate
        topk_kernel<<<B_, NP_>>>(bp, l);
        // qkv = feats_l @ [Wq|Wk|Wv]  (tf32 tensor cores — post-ordering, safe)
        const float* fl = pfeats + (size_t)l*B_*DIMS_*H_;
        qkv_wmma<<<dim3(B_*DIMS_/64, 6), 128, QKV_SMEM>>>(fl, pWqkv, pqkv);
        // attention -> feats_l
        attn_kernel<<<B_*HEADS_, 256, ATTN_SMEM>>>(l);
    }

    head_kernel<<<B_, 128>>>(Wc1, bc1, Wc2, bc2, Wl1, bl1, Wl2, bl2, (float*)d_out);
}

// round 5
// speedup vs baseline: 1.2812x; 1.0526x over previous
#include <cuda_runtime.h>
#include <math.h>

#define B_    128
#define NP_   256
#define NN    (B_*NP_)
#define H_    128
#define DIMS_ 128
#define HEADS_ 8
#define DK_   16
#define C1_   32
#define C2_   64
#define NC_   10
#define EPG   4096
#define ETOT  (B_*EPG)
#define PPAD  132

// ------------------- device scratch -------------------
__device__ float g_deg[NN];
__device__ float g_dnorm[NN];
__device__ int   g_off[NN];
__device__ int   g_cur[NN];
__device__ unsigned short g_csr[ETOT];
__device__ float g_h[(size_t)NN*H_];
__device__ float g_feats[(size_t)3*B_*DIMS_*H_];
__device__ float g_qkv[(size_t)B_*DIMS_*384];
__device__ float g_Wqkv[(size_t)H_*384];

// ------------------- prep -------------------
__global__ void zero_kernel() {
    int i = blockIdx.x * blockDim.x + threadIdx.x;
    if (i < NN) { g_deg[i] = 0.f; g_cur[i] = 0; }
}
__global__ void deg_kernel(const int* __restrict__ dst, int E) {
    int e = blockIdx.x * blockDim.x + threadIdx.x;
    if (e < E) atomicAdd(&g_deg[dst[e]], 1.0f);
}
// scan (CSR offsets) + dnorm fused
__global__ void scan_kernel() {
    int g = blockIdx.x, t = threadIdx.x;
    __shared__ int a[NP_];
    int node = g*NP_ + t;
    float degf = g_deg[node];
    int v = (int)degf;
    a[t] = v;
    __syncthreads();
    for (int off = 1; off < NP_; off <<= 1) {
        int x = a[t];
        if (t >= off) x += a[t - off];
        __syncthreads();
        a[t] = x;
        __syncthreads();
    }
    g_off[node] = g*EPG + a[t] - v;
    g_dnorm[node] = rsqrtf(fmaxf(degf, 1.0f));
}
// scatter edges into CSR + pack Wqkv (independent work, fused to cut a launch)
__global__ void scatter_kernel(const int* __restrict__ src, const int* __restrict__ dst, int E,
                               const float* __restrict__ Wq, const float* __restrict__ Wk,
                               const float* __restrict__ Wv) {
    int e = blockIdx.x * blockDim.x + threadIdx.x;
    if (e < E) {
        int s = src[e], d = dst[e];
        int pos = atomicAdd(&g_cur[d], 1);
        g_csr[g_off[d] + pos] = (unsigned short)(s & 255);
    }
    if (e < H_*H_) {
        int k = e >> 7, c = e & 127;
        g_Wqkv[k*384 + c]       = Wq[e];
        g_Wqkv[k*384 + 128 + c] = Wk[e];
        g_Wqkv[k*384 + 256 + c] = Wv[e];
    }
}

// ------------------- mega-fused layer kernel -------------------
// One block per graph (512 threads). Phases:
//  1. stage W (64KB) + h-tile (135KB, pad 132) + dnorm into smem
//  2. in-place GEMM pre = h @ W (k ascending, identical order to gemm128),
//     writeback scaled by dnorm[src]
//  3. CSR aggregation -> h_new = relu(dnorm*sum + b) -> global; fused sp = h_new @ Wp
//  4. score = dnorm * sum_neighbors(sp*dnorm) + bp
//  5. bitonic top-k (desc value, asc index)  6. gather + tanh gate -> feats
__global__ void __launch_bounds__(512, 1)
layer_kernel(const float* __restrict__ hin, const float* __restrict__ W,
             const float* __restrict__ bias, const float* __restrict__ Wp,
             const float* __restrict__ bp, float* __restrict__ hout, int layer)
{
    extern __shared__ float sm[];
    float* P   = sm;                       // [256][132]
    float* Wm  = P + 256*PPAD;             // [128][128]
    float* dn  = Wm + 128*128;             // [256]
    float* sps = dn + 256;                 // [256]
    float* ssh = sps + 256;                // [256]
    float* v   = ssh + 256;                // [256]
    float* gate= v + 256;                  // [128]
    int*   ix  = (int*)(gate + 128);       // [256]

    int g = blockIdx.x, t = threadIdx.x;   // 512 threads

    // ---- phase 1: stage ----
    for (int i = t; i < 128*32; i += 512)
        ((float4*)Wm)[i] = ((const float4*)W)[i];
    if (t < 256) dn[t] = g_dnorm[g*NP_ + t];
    {
        const float4* h4 = (const float4*)(hin + (size_t)g*NP_*H_);
        for (int i = t; i < 256*32; i += 512) {
            int r = i >> 5, c = i & 31;
            *(float4*)&P[r*PPAD + c*4] = h4[i];
        }
    }
    __syncthreads();

    // ---- phase 2: in-place GEMM pre = h @ W, then scale by dnorm[src] ----
    {
        int r = t & 255, half = t >> 8;
        float acc[64];
        #pragma unroll
        for (int j = 0; j < 64; j++) acc[j] = 0.f;
        const float* arow = &P[r*PPAD];
        for (int k = 0; k < 128; k++) {
            float a = arow[k];
            const float4* wr4 = (const float4*)(Wm + k*128 + half*64);
            #pragma unroll
            for (int j4 = 0; j4 < 16; j4++) {
                float4 w4 = wr4[j4];
                acc[j4*4+0] += a * w4.x;
                acc[j4*4+1] += a * w4.y;
                acc[j4*4+2] += a * w4.z;
                acc[j4*4+3] += a * w4.w;
            }
        }
        __syncthreads();   // all reads of h done before overwrite
        float sc = dn[r];
        float4* prow4 = (float4*)(P + r*PPAD + half*64);
        #pragma unroll
        for (int j4 = 0; j4 < 16; j4++)
            prow4[j4] = make_float4(acc[j4*4+0]*sc, acc[j4*4+1]*sc,
                                    acc[j4*4+2]*sc, acc[j4*4+3]*sc);
    }
    __syncthreads();

    // ---- phase 3: CSR aggregation + relu + bias, fused sp projection ----
    {
        int warp = t >> 5, lane = t & 31;   // 16 warps x 16 nodes
        float4 bv = ((const float4*)bias)[lane];
        float4 wp = ((const float4*)Wp)[lane];
        for (int d0 = warp*16; d0 < warp*16 + 16; d0 += 4) {
            int beg[4], len[4];
            float4 acc[4];
            int maxlen = 0;
            #pragma unroll
            for (int j = 0; j < 4; j++) {
                int node = g*NP_ + d0 + j;
                beg[j] = g_off[node];
                len[j] = (int)g_deg[node];
                maxlen = max(maxlen, len[j]);
                acc[j] = make_float4(0.f, 0.f, 0.f, 0.f);
            }
            for (int i = 0; i < maxlen; i++) {
                #pragma unroll
                for (int j = 0; j < 4; j++) {
                    if (i < len[j]) {
                        int s = g_csr[beg[j] + i];
                        float4 vv = *(const float4*)&P[s*PPAD + lane*4];
                        acc[j].x += vv.x; acc[j].y += vv.y; acc[j].z += vv.z; acc[j].w += vv.w;
                    }
                }
            }
            #pragma unroll
            for (int j = 0; j < 4; j++) {
                int node = g*NP_ + d0 + j;
                float sc = dn[d0 + j];
                float4 o;
                o.x = fmaxf(acc[j].x*sc + bv.x, 0.f);
                o.y = fmaxf(acc[j].y*sc + bv.y, 0.f);
                o.z = fmaxf(acc[j].z*sc + bv.z, 0.f);
                o.w = fmaxf(acc[j].w*sc + bv.w, 0.f);
                ((float4*)hout)[(size_t)node*32 + lane] = o;
                float s = o.x*wp.x + o.y*wp.y + o.z*wp.z + o.w*wp.w;
                #pragma unroll
                for (int off = 16; off; off >>= 1) s += __shfl_down_sync(0xffffffffu, s, off);
                if (lane == 0) sps[d0 + j] = s;
            }
        }
    }
    __syncthreads();

    // ---- phase 4: score via CSR ----
    if (t < 256) ssh[t] = sps[t] * dn[t];
    __syncthreads();
    if (t < 256) {
        int node = g*NP_ + t;
        int beg = g_off[node], len = (int)g_deg[node];
        float s = 0.f;
        for (int i = 0; i < len; i++) s += ssh[g_csr[beg + i]];
        v[t]  = s * dn[t] + bp[0];
        ix[t] = t;
    }
    __syncthreads();

    // ---- phase 5: bitonic sort (desc value, asc index) ----
    for (int k = 2; k <= NP_; k <<= 1) {
        for (int j = k >> 1; j > 0; j >>= 1) {
            if (t < 256) {
                int p = t ^ j;
                if (p > t) {
                    bool dirDesc = ((t & k) == 0);
                    float v1 = v[t], v2 = v[p];
                    int i1 = ix[t], i2 = ix[p];
                    bool a_gt = (v1 > v2) || (v1 == v2 && i1 < i2);
                    if (dirDesc != a_gt) {
                        v[t] = v2; v[p] = v1; ix[t] = i2; ix[p] = i1;
                    }
                }
            }
            __syncthreads();
        }
    }
    if (t < 128) gate[t] = tanhf(v[t]);
    __syncthreads();

    // ---- phase 6: gather + gate -> feats ----
    float* dstp = g_feats + (size_t)(layer*B_ + g)*DIMS_*H_;
    for (int e = t; e < DIMS_*H_; e += 512) {
        int j = e >> 7, c = e & 127;
        dstp[e] = hout[((size_t)g*NP_ + ix[j])*H_ + c] * gate[j];
    }
}

// ------------------- fp32 SGEMM (QKV): 128x128 tile, 8x8/thread -------------------
__global__ void gemm128(const float* __restrict__ A, const float* __restrict__ B,
                        float* __restrict__ C, int M, int Nn, int K)
{
    __shared__ float As[8][128];
    __shared__ float Bs[8][128];
    int t = threadIdx.x;
    int m0 = blockIdx.x * 128, n0 = blockIdx.y * 128;
    int tx = t & 15, ty = t >> 4;
    int arow = t >> 1, aseg = t & 1;
    int brow = t >> 5, bcol = t & 31;
    float acc[8][8];
    #pragma unroll
    for (int i = 0; i < 8; i++)
        #pragma unroll
        for (int j = 0; j < 8; j++) acc[i][j] = 0.f;

    for (int k0 = 0; k0 < K; k0 += 8) {
        float4 av  = *(const float4*)(A + (size_t)(m0 + arow)*K + k0 + aseg*4);
        float4 bvv = *(const float4*)(B + (size_t)(k0 + brow)*Nn + n0 + bcol*4);
        As[aseg*4+0][arow] = av.x;
        As[aseg*4+1][arow] = av.y;
        As[aseg*4+2][arow] = av.z;
        As[aseg*4+3][arow] = av.w;
        *(float4*)&Bs[brow][bcol*4] = bvv;
        __syncthreads();
        #pragma unroll
        for (int k = 0; k < 8; k++) {
            float a[8], bb[8];
            *(float4*)(a)    = *(float4*)&As[k][ty*8];
            *(float4*)(a+4)  = *(float4*)&As[k][ty*8+4];
            *(float4*)(bb)   = *(float4*)&Bs[k][tx*8];
            *(float4*)(bb+4) = *(float4*)&Bs[k][tx*8+4];
            #pragma unroll
            for (int i = 0; i < 8; i++)
                #pragma unroll
                for (int j = 0; j < 8; j++) acc[i][j] += a[i]*bb[j];
        }
        __syncthreads();
    }
    #pragma unroll
    for (int i = 0; i < 8; i++) {
        float* cp = C + (size_t)(m0 + ty*8 + i)*Nn + n0 + tx*8;
        *(float4*)cp     = make_float4(acc[i][0], acc[i][1], acc[i][2], acc[i][3]);
        *(float4*)(cp+4) = make_float4(acc[i][4], acc[i][5], acc[i][6], acc[i][7]);
    }
}

// ------------------- fast exp on FMA pipe -------------------
__device__ __forceinline__ float fast_exp(float x) {
    float y = x * 1.4426950408889634f;
    if (y < -120.f) return 0.f;
    float n = rintf(y);
    float r = (y - n) * 0.6931471805599453f;
    float p = 1.f/720.f;
    p = p*r + 1.f/120.f;
    p = p*r + 1.f/24.f;
    p = p*r + 1.f/6.f;
    p = p*r + 0.5f;
    p = p*r + 1.f;
    p = p*r + 1.f;
    int e = (int)n;
    float s = __int_as_float((e + 127) << 23);
    return p * s;
}

// ------------------- attention: one block per (graph, head) -------------------
#define SSTR 129
__global__ void attn_kernel(int layer) {
    extern __shared__ float asm_[];
    float* ksh  = asm_;                    // [128][16]
    float* vsh  = asm_ + 2048;             // [128][16]
    float* S    = asm_ + 4096;             // [128][129]
    float* rsum = asm_ + 4096 + 128*SSTR;  // [128]

    int bh = blockIdx.x;
    int b = bh >> 3, hd = bh & 7;
    int t = threadIdx.x;                   // 256 threads
    const float* qkv = g_qkv + (size_t)b * DIMS_ * 384;

    for (int e = t; e < DIMS_*DK_; e += 256) {
        int m = e >> 4, d = e & 15;
        ksh[m*DK_ + d] = qkv[(size_t)m*384 + 128 + hd*DK_ + d];
        vsh[m*DK_ + d] = qkv[(size_t)m*384 + 256 + hd*DK_ + d];
    }
    __syncthreads();

    int q = t >> 1, half = t & 1;
    float qv[DK_];
    #pragma unroll
    for (int d = 0; d < DK_; d++) qv[d] = qkv[(size_t)q*384 + hd*DK_ + d];
    float lmax = -INFINITY;
    #pragma unroll 4
    for (int i = 0; i < 64; i++) {
        int m = half*64 + i;
        float s = 0.f;
        #pragma unroll
        for (int d = 0; d < DK_; d++) s += qv[d]*ksh[m*DK_ + d];
        s *= 0.25f;
        S[q*SSTR + m] = s;
        lmax = fmaxf(lmax, s);
    }
    float rmax = fmaxf(lmax, __shfl_xor_sync(0xffffffffu, lmax, 1));
    float lsum = 0.f;
    #pragma unroll 4
    for (int i = 0; i < 64; i++) {
        int m = half*64 + i;
        float p = fast_exp(S[q*SSTR + m] - rmax);
        S[q*SSTR + m] = p;
        lsum += p;
    }
    lsum += __shfl_xor_sync(0xffffffffu, lsum, 1);
    if (half == 0) rsum[q] = lsum;
    __syncthreads();

    int q2 = t & 127, dh = t >> 7;
    float acc[8];
    #pragma unroll
    for (int j = 0; j < 8; j++) acc[j] = 0.f;
    for (int m = 0; m < 128; m++) {
        float p = S[q2*SSTR + m];
        #pragma unroll
        for (int j = 0; j < 8; j++) acc[j] += p * vsh[m*DK_ + dh*8 + j];
    }
    float inv = 1.f / rsum[q2];
    float* ob = g_feats + (size_t)(layer*B_ + b)*DIMS_*H_ + (size_t)q2*H_ + hd*DK_ + dh*8;
    *(float4*)ob     = make_float4(acc[0]*inv, acc[1]*inv, acc[2]*inv, acc[3]*inv);
    *(float4*)(ob+4) = make_float4(acc[4]*inv, acc[5]*inv, acc[6]*inv, acc[7]*inv);
}

// ------------------- fused classifier head -------------------
__global__ void head_kernel(const float* __restrict__ Wc1, const float* __restrict__ bc1,
                            const float* __restrict__ Wc2, const float* __restrict__ bc2,
                            const float* __restrict__ Wl1, const float* __restrict__ bl1,
                            const float* __restrict__ Wl2, const float* __restrict__ bl2,
                            float* __restrict__ out)
{
    int b = blockIdx.x;
    int t = threadIdx.x;
    __shared__ float ysh[C1_][H_];
    __shared__ float ypsh[C1_][H_/2];
    __shared__ float partial[128];
    __shared__ float z0[C2_];
    __shared__ float z1s[C2_];
    __shared__ float vv[NC_];

    float acc[C1_];
    #pragma unroll
    for (int o = 0; o < C1_; o++) acc[o] = 0.f;
    for (int c = 0; c < 3; c++) {
        const float* fb = g_feats + (size_t)(c*B_ + b)*DIMS_*H_;
        for (int d = 0; d < DIMS_; d++) {
            float xv = fb[(size_t)d*H_ + t];
            int cd = c*DIMS_ + d;
            #pragma unroll
            for (int o = 0; o < C1_; o++) acc[o] += Wc1[o*384 + cd] * xv;
        }
    }
    #pragma unroll
    for (int o = 0; o < C1_; o++) ysh[o][t] = fmaxf(acc[o] + bc1[o], 0.f);
    __syncthreads();

    if (t < H_/2) {
        #pragma unroll
        for (int o = 0; o < C1_; o++)
            ypsh[o][t] = fmaxf(ysh[o][2*t], ysh[o][2*t+1]);
    }
    __syncthreads();

    {
        int o2 = t & 63, halfq = t >> 6;
        float s2 = 0.f;
        for (int c = halfq*16; c < halfq*16 + 16; c++) {
            const float* wrow = Wc2 + ((size_t)o2*C1_ + c)*64;
            #pragma unroll
            for (int w = 0; w < 64; w++) s2 += ypsh[c][w] * wrow[w];
        }
        partial[t] = s2;
    }
    __syncthreads();
    if (t < C2_) z0[t] = fmaxf(partial[t] + partial[t+64] + bc2[t], 0.f);
    __syncthreads();

    if (t < C2_) {
        float s = bl1[t];
        #pragma unroll
        for (int i = 0; i < C2_; i++) s += z0[i] * Wl1[i*C2_ + t];
        z1s[t] = fmaxf(s, 0.f);
    }
    __syncthreads();

    if (t < NC_) {
        float s = bl2[t];
        #pragma unroll
        for (int i = 0; i < C2_; i++) s += z1s[i] * Wl2[i*NC_ + t];
        vv[t] = s;
    }
    __syncthreads();

    if (t == 0) {
        float mx = vv[0];
        for (int i = 1; i < NC_; i++) mx = fmaxf(mx, vv[i]);
        float se = 0.f;
        for (int i = 0; i < NC_; i++) se += expf(vv[i] - mx);
        float ls = logf(se);
        for (int i = 0; i < NC_; i++) out[b*NC_ + i] = vv[i] - mx - ls;
    }
}

// ------------------- host driver -------------------
extern "C" void kernel_launch(void* const* d_in, const int* in_sizes, int n_in,
                              void* d_out, int out_size)
{
    const float* x   = (const float*)d_in[0];
    const int*   src = (const int*)d_in[1];
    const int*   dst = (const int*)d_in[2];
    const float* Wg[3] = {(const float*)d_in[3], (const float*)d_in[5], (const float*)d_in[7]};
    const float* bg[3] = {(const float*)d_in[4], (const float*)d_in[6], (const float*)d_in[8]};
    const float* Wp  = (const float*)d_in[9];
    const float* bp  = (const float*)d_in[10];
    const float* Wq  = (const float*)d_in[11];
    const float* Wk  = (const float*)d_in[12];
    const float* Wv  = (const float*)d_in[13];
    const float* Wc1 = (const float*)d_in[14];
    const float* bc1 = (const float*)d_in[15];
    const float* Wc2 = (const float*)d_in[16];
    const float* bc2 = (const float*)d_in[17];
    const float* Wl1 = (const float*)d_in[18];
    const float* bl1 = (const float*)d_in[19];
    const float* Wl2 = (const float*)d_in[20];
    const float* bl2 = (const float*)d_in[21];
    int E = in_sizes[1];

    float *ph, *pqkv, *pfeats, *pWqkv;
    cudaGetSymbolAddress((void**)&ph,     g_h);
    cudaGetSymbolAddress((void**)&pqkv,   g_qkv);
    cudaGetSymbolAddress((void**)&pfeats, g_feats);
    cudaGetSymbolAddress((void**)&pWqkv,  g_Wqkv);

    const int LAYER_SMEM = (256*PPAD + 128*128 + 256 + 256 + 256 + 256 + 128 + 256) * (int)sizeof(float);
    const int ATTN_SMEM  = (4096 + 128*SSTR + 128) * (int)sizeof(float);
    cudaFuncSetAttribute(layer_kernel, cudaFuncAttributeMaxDynamicSharedMemorySize, LAYER_SMEM);
    cudaFuncSetAttribute(attn_kernel,  cudaFuncAttributeMaxDynamicSharedMemorySize, ATTN_SMEM);

    zero_kernel<<<(NN + 255)/256, 256>>>();
    deg_kernel<<<(E + 255)/256, 256>>>(dst, E);
    scan_kernel<<<B_, NP_>>>();
    scatter_kernel<<<(E + 255)/256, 256>>>(src, dst, E, Wq, Wk, Wv);

    for (int l = 0; l < 3; l++) {
        const float* hin = (l == 0) ? x : ph;
        // fused: GEMM + aggregation + score + top-k + gather/gate
        layer_kernel<<<B_, 512, LAYER_SMEM>>>(hin, Wg[l], bg[l], Wp, bp, ph, l);
        // qkv = feats_l @ [Wq|Wk|Wv]
        const float* fl = pfeats + (size_t)l*B_*DIMS_*H_;
        gemm128<<<dim3(B_*DIMS_/128, 3), 256>>>(fl, pWqkv, pqkv, B_*DIMS_, 384, H_);
        // attention -> feats_l
        attn_kernel<<<B_*HEADS_, 256, ATTN_SMEM>>>(l);
    }

    head_kernel<<<B_, 128>>>(Wc1, bc1, Wc2, bc2, Wl1, bl1, Wl2, bl2, (float*)d_out);
}